// round 9
// baseline (speedup 1.0000x reference)
#include <cuda_runtime.h>
#include <cuda_fp16.h>

#define NPTS 8192
#define DIM  128
#define TILE 128
#define NT   (NPTS/TILE)          // 64
#define NTILES (NT*(NT+1)/2)      // 2080
#define MARGIN 1.0f
#define EPSV 1e-16f
#define PAIR_CAP 2500000

// ---------------- device scratch ----------------
__device__ float g_S[NPTS];
__device__ float g_sq[NPTS];
__device__ int   g_lab[NPTS];
__device__ double g_loss;
__device__ unsigned long long g_cnt;
__device__ unsigned g_np;
__device__ unsigned g_done;
__device__ unsigned g_bar1;
__device__ unsigned g_bar2;
__device__ uint4 g_h[NPTS*DIM/8];    // fp16 features, 8 per uint4
__device__ uint2 g_pairs[PAIR_CAP];

// ---------------- smem layout (bytes) ----------------
// A 32K | B[2] 2x32K | misc | pbuf 8K  (2 CTAs/SM)
#define SM_AH   0
#define SM_B(b) (32768 + (b)*32768)
#define SM_MISC 98304
#define SM_SQI  (SM_MISC)
#define SM_LI   (SM_MISC + 512)
#define SM_SQJ  (SM_MISC + 1024)
#define SM_LJ   (SM_MISC + 1536)
#define SM_ROWS (SM_MISC + 2048)
#define SM_COLS (SM_MISC + 2560)
#define SM_CNT  (SM_MISC + 3072)
#define SM_GB   (SM_MISC + 3076)
#define SM_PBUF (SM_MISC + 3104)
#define PBUF_CAP 1024
#define SM_TOTAL (SM_PBUF + PBUF_CAP*8)

__device__ __forceinline__ unsigned smem_u32(const void* p) {
    unsigned a;
    asm("{ .reg .u64 t; cvta.to.shared.u64 t, %1; cvt.u32.u64 %0, t; }" : "=r"(a) : "l"(p));
    return a;
}

#define LDGSTS16(dst, src) asm volatile("cp.async.cg.shared.global [%0], [%1], 16;" :: "r"(dst), "l"(src) : "memory")
#define CP_COMMIT() asm volatile("cp.async.commit_group;" ::: "memory")
#define CP_WAIT1()  asm volatile("cp.async.wait_group 1;" ::: "memory")
#define CP_WAIT0()  asm volatile("cp.async.wait_group 0;" ::: "memory")

#define LDSM4(R, a) asm volatile( \
    "ldmatrix.sync.aligned.m8n8.x4.shared.b16 {%0,%1,%2,%3}, [%4];" \
    : "=r"((R)[0]), "=r"((R)[1]), "=r"((R)[2]), "=r"((R)[3]) : "r"(a))

#define MMA(d, a, b) asm volatile( \
    "mma.sync.aligned.m16n8k16.row.col.f32.f16.f16.f32 " \
    "{%0,%1,%2,%3}, {%4,%5,%6,%7}, {%8,%9}, {%0,%1,%2,%3};" \
    : "+f"((d)[0]), "+f"((d)[1]), "+f"((d)[2]), "+f"((d)[3]) \
    : "r"((a)[0]), "r"((a)[1]), "r"((a)[2]), "r"((a)[3]), "r"((b)[0]), "r"((b)[1]))

// grid-wide barrier: all CTAs resident (launch_bounds(256,2), grid = 2*SMs)
__device__ __forceinline__ void grid_barrier(unsigned* bar, int t, unsigned target) {
    __syncthreads();
    if (t == 0) {
        __threadfence();
        atomicAdd(bar, 1u);
        while (*(volatile unsigned*)bar < target) __nanosleep(32);
    }
    __syncthreads();
}

// ---------------- stage helpers ----------------
// 256B rows, 16B granules, swizzle: granule q at row r -> q ^ (r&7)
__device__ __forceinline__ void issue_B(unsigned sb, int buf, int jt, int t) {
    const char* sh = (const char*)(g_h + (size_t)jt * 2048);
    const unsigned db = sb + SM_B(buf);
    #pragma unroll
    for (int i = 0; i < 8; i++) {
        int g = i * 256 + t;
        int r = g >> 4, q = g & 15;
        unsigned dsw = (unsigned)(r * 256 + ((q ^ (r & 7)) << 4));
        LDGSTS16(db + dsw, sh + (size_t)g * 16);
    }
}
__device__ __forceinline__ void load_A(char* smem, int it, int t) {
    const uint4* sh = g_h + (size_t)it * 2048;
    #pragma unroll
    for (int i = 0; i < 8; i++) {
        int g = i * 256 + t;
        int r = g >> 4, q = g & 15;
        unsigned dsw = (unsigned)(r * 256 + ((q ^ (r & 7)) << 4));
        *(uint4*)(smem + SM_AH + dsw) = sh[g];
    }
}

// ---------------- single fused persistent kernel ----------------
__global__ void __launch_bounds__(256, 2) k_all(const float* __restrict__ f,
                                                const int* __restrict__ lab32,
                                                float* __restrict__ out) {
    extern __shared__ char smem[];
    const unsigned sb = smem_u32(smem);
    float* s_sqi  = (float*)(smem + SM_SQI);
    int*   s_li   = (int*)  (smem + SM_LI);
    float* s_sqj  = (float*)(smem + SM_SQJ);
    int*   s_lj   = (int*)  (smem + SM_LJ);
    float* s_rowS = (float*)(smem + SM_ROWS);
    float* s_colS = (float*)(smem + SM_COLS);
    unsigned* s_cnt = (unsigned*)(smem + SM_CNT);
    unsigned* s_gb  = (unsigned*)(smem + SM_GB);
    uint2* pbuf = (uint2*)(smem + SM_PBUF);

    const int t = threadIdx.x, w = t >> 5, lane = t & 31;
    const int gid = blockIdx.x * 256 + t;
    const int nth = gridDim.x * 256;
    const unsigned ngrid = gridDim.x;

    // ======== phase A: prep (fp16 convert + sq + labels + init) ========
    {
        // label dtype detect: per-block sample of 256 odd 32-bit words
        int odd = lab32[2 * t + 1];
        int nz = __syncthreads_or(odd != 0);     // nz -> int32 labels
        int step = nz ? 1 : 2;
        for (int i = gid; i < NPTS; i += nth) g_lab[i] = lab32[i * step];

        // row-per-thread: convert + squared norm
        for (int row = gid; row < NPTS; row += nth) {
            const float4* fr = (const float4*)(f + (size_t)row * DIM);
            float s = 0.0f;
            #pragma unroll
            for (int q = 0; q < 16; q++) {
                float4 a = fr[q * 2], c = fr[q * 2 + 1];
                s = fmaf(a.x, a.x, s); s = fmaf(a.y, a.y, s);
                s = fmaf(a.z, a.z, s); s = fmaf(a.w, a.w, s);
                s = fmaf(c.x, c.x, s); s = fmaf(c.y, c.y, s);
                s = fmaf(c.z, c.z, s); s = fmaf(c.w, c.w, s);
                __half2 h0 = __floats2half2_rn(a.x, a.y);
                __half2 h1 = __floats2half2_rn(a.z, a.w);
                __half2 h2 = __floats2half2_rn(c.x, c.y);
                __half2 h3 = __floats2half2_rn(c.z, c.w);
                g_h[(size_t)row * 16 + q] =
                    make_uint4(*(unsigned*)&h0, *(unsigned*)&h1, *(unsigned*)&h2, *(unsigned*)&h3);
            }
            g_sq[row] = s;
            g_S[row] = 0.0f;
        }
        if (gid == 0) { g_loss = 0.0; g_cnt = 0ull; g_np = 0u; g_done = 0u; }
    }
    grid_barrier(&g_bar1, t, ngrid);

    // ======== phase B: tiles ========
    {
        const int basec = NTILES / (int)ngrid, rem = NTILES % (int)ngrid;
        const int start = blockIdx.x * basec + min((int)blockIdx.x, rem);
        const int end = start + basec + ((int)blockIdx.x < rem ? 1 : 0);

        int cit = 0, base = 0;
        while (start >= base + (NT - cit)) { base += NT - cit; cit++; }
        int cjt = cit + (start - base);

        // prefetch pipeline (depth 2)
        int pit = cit, pjt = cjt;
        issue_B(sb, start & 1, pjt, t); CP_COMMIT();
        { pjt++; if (pjt == NT) { pit++; pjt = pit; } }
        if (start + 1 < end) {
            issue_B(sb, (start + 1) & 1, pjt, t); CP_COMMIT();
            pjt++; if (pjt == NT) { pit++; pjt = pit; }
        }

        // warp subtile: 32 rows x 64 cols
        const int mb = (w & 3) * 32;
        const int nb = (w >> 2) * 64;
        const int a_row = mb + (lane & 15);
        const int a_ch  = lane >> 4;
        const int b_row = nb + (lane & 7) + ((lane >> 4) << 3);
        const int b_ch  = (lane >> 3) & 1;

        int curA = -1;

        for (int k = start; k < end; k++) {
            const int buf = k & 1;
            const bool offdiag = (cit != cjt);
            if (k + 1 < end) CP_WAIT1(); else CP_WAIT0();

            if (cit != curA) {
                __syncthreads();
                if (curA >= 0 && t < 128) atomicAdd(&g_S[curA * TILE + t], s_rowS[t]);
                load_A(smem, cit, t);
                if (t < 128) {
                    s_sqi[t] = g_sq[cit * TILE + t];
                    s_li[t]  = g_lab[cit * TILE + t];
                    s_rowS[t] = 0.0f;
                }
                curA = cit;
            }
            if (t < 128) {
                s_sqj[t] = g_sq[cjt * TILE + t];
                s_lj[t]  = g_lab[cjt * TILE + t];
                s_colS[t] = 0.0f;
            }
            if (t == 0) *s_cnt = 0u;
            __syncthreads();

            // ---- MMA ----
            float acc[2][8][4];
            #pragma unroll
            for (int mt = 0; mt < 2; mt++)
                #pragma unroll
                for (int nt = 0; nt < 8; nt++)
                    #pragma unroll
                    for (int e = 0; e < 4; e++) acc[mt][nt][e] = 0.0f;

            const unsigned bbase = sb + SM_B(buf);
            #pragma unroll
            for (int ks = 0; ks < 8; ks++) {
                unsigned ah[2][4], bh[8][2];
                #pragma unroll
                for (int mt = 0; mt < 2; mt++) {
                    int r = a_row + mt * 16;
                    unsigned addr = sb + SM_AH + r * 256 + (((ks * 2 + a_ch) ^ (r & 7)) << 4);
                    LDSM4(ah[mt], addr);
                }
                #pragma unroll
                for (int np = 0; np < 4; np++) {
                    int r = b_row + np * 16;
                    unsigned addr = bbase + r * 256 + (((ks * 2 + b_ch) ^ (r & 7)) << 4);
                    unsigned th[4];
                    LDSM4(th, addr);
                    bh[2*np][0] = th[0]; bh[2*np][1] = th[1];
                    bh[2*np+1][0] = th[2]; bh[2*np+1][1] = th[3];
                }
                #pragma unroll
                for (int mt = 0; mt < 2; mt++)
                    #pragma unroll
                    for (int nt = 0; nt < 8; nt++)
                        MMA(acc[mt][nt], ah[mt], bh[nt]);
            }
            __syncthreads();   // all warps done reading B(buf)

            // prefetch B(k+2); overlaps epilogue
            if (k + 2 < end) {
                issue_B(sb, buf, pjt, t); CP_COMMIT();
                pjt++; if (pjt == NT) { pit++; pjt = pit; }
            }

            // ---- epilogue ----
            const int r4 = lane >> 2, cb = (lane & 3) * 2;
            float sqi_r[4]; int li_r[4];
            #pragma unroll
            for (int mt = 0; mt < 2; mt++)
                #pragma unroll
                for (int h = 0; h < 2; h++) {
                    int iL = mb + mt * 16 + r4 + h * 8;
                    sqi_r[mt*2+h] = s_sqi[iL]; li_r[mt*2+h] = s_li[iL];
                }

            float rp[4] = {0.f, 0.f, 0.f, 0.f};
            float cp[16];
            #pragma unroll
            for (int q = 0; q < 16; q++) cp[q] = 0.0f;

            #pragma unroll
            for (int mt = 0; mt < 2; mt++)
                #pragma unroll
                for (int nt = 0; nt < 8; nt++)
                    #pragma unroll
                    for (int e = 0; e < 4; e++) {
                        const int h = e >> 1, o = e & 1;
                        const int jL = nb + nt * 8 + cb + o;
                        float d2 = fmaxf(sqi_r[mt*2+h] + s_sqj[jL] - 2.0f * acc[mt][nt][e], EPSV);
                        float d;
                        asm("sqrt.approx.f32 %0, %1;" : "=f"(d) : "f"(d2));
                        if (li_r[mt*2+h] != s_lj[jL]) {
                            float ex = __expf(MARGIN - d);
                            rp[mt*2+h] += ex;
                            cp[nt*2+o] += ex;
                        } else {
                            unsigned kk = atomicAdd(s_cnt, 1u);
                            unsigned gi = cit * TILE + mb + mt * 16 + r4 + h * 8;
                            unsigned gj = cjt * TILE + jL;
                            unsigned packed = gi | (gj << 13) | (offdiag ? (1u << 26) : 0u);
                            uint2 rec = make_uint2(packed, __float_as_uint(d));
                            if (kk < PBUF_CAP) pbuf[kk] = rec;
                            else { unsigned gg = atomicAdd(&g_np, 1u); if (gg < PAIR_CAP) g_pairs[gg] = rec; }
                        }
                    }

            #pragma unroll
            for (int q = 0; q < 4; q++) {
                float v = rp[q];
                v += __shfl_xor_sync(0xffffffffu, v, 1);
                v += __shfl_xor_sync(0xffffffffu, v, 2);
                if ((lane & 3) == 0)
                    atomicAdd(&s_rowS[mb + (q >> 1) * 16 + r4 + (q & 1) * 8], v);
            }
            if (offdiag) {
                #pragma unroll
                for (int q = 0; q < 16; q++) {
                    float v = cp[q];
                    v += __shfl_xor_sync(0xffffffffu, v, 4);
                    v += __shfl_xor_sync(0xffffffffu, v, 8);
                    v += __shfl_xor_sync(0xffffffffu, v, 16);
                    if ((lane >> 2) == 0)
                        atomicAdd(&s_colS[nb + (q >> 1) * 8 + cb + (q & 1)], v);
                }
            }
            __syncthreads();

            if (offdiag && t < 128) atomicAdd(&g_S[cjt * TILE + t], s_colS[t]);

            // flush pair buffer
            unsigned cnt = *s_cnt;
            if (cnt > PBUF_CAP) cnt = PBUF_CAP;
            if (t == 0) *s_gb = atomicAdd(&g_np, cnt);
            __syncthreads();
            unsigned gbv = *s_gb;
            for (unsigned k2 = t; k2 < cnt; k2 += 256)
                if (gbv + k2 < PAIR_CAP) g_pairs[gbv + k2] = pbuf[k2];
            __syncthreads();

            cjt++; if (cjt == NT) { cit++; cjt = cit; }
        }

        if (curA >= 0 && t < 128) atomicAdd(&g_S[curA * TILE + t], s_rowS[t]);
    }
    grid_barrier(&g_bar2, t, ngrid);

    // ======== phase C: positive-pair loss + finalize ========
    {
        float* rf = (float*)(smem + SM_PBUF);           // reuse smem
        int*   ri = (int*)(smem + SM_PBUF + 1024);
        unsigned n = g_np; if (n > PAIR_CAP) n = PAIR_CAP;
        float part = 0.0f; int c = 0;
        for (unsigned idx = blockIdx.x * 256u + t; idx < n; idx += ngrid * 256u) {
            uint2 p = g_pairs[idx];
            int i = p.x & 0x1FFF, j = (p.x >> 13) & 0x1FFF;
            int wt = (p.x & (1u << 26)) ? 2 : 1;
            float d = __uint_as_float(p.y);
            float J = logf(g_S[i] + g_S[j]) + d;
            float h = fmaxf(J, 0.0f);
            part += (float)wt * h * h; c += wt;
        }
        rf[t] = part; ri[t] = c;
        __syncthreads();
        for (int off = 128; off; off >>= 1) {
            if (t < off) { rf[t] += rf[t + off]; ri[t] += ri[t + off]; }
            __syncthreads();
        }
        if (t == 0) {
            atomicAdd(&g_loss, (double)rf[0]);
            atomicAdd(&g_cnt, (unsigned long long)ri[0]);
            __threadfence();
            unsigned v = atomicAdd(&g_done, 1u);
            if (v == ngrid - 1) {
                out[0] = (float)(g_loss / (2.0 * (double)g_cnt));
                g_bar1 = 0u; g_bar2 = 0u;            // reset for next graph replay
            }
        }
    }
}

// ---------------- launcher ----------------
extern "C" void kernel_launch(void* const* d_in, const int* in_sizes, int n_in,
                              void* d_out, int out_size) {
    const float* f     = (const float*)d_in[0];
    const int*   lab32 = (const int*)d_in[1];
    float*       out   = (float*)d_out;

    int dev = 0, nsm = 0;
    if (cudaGetDevice(&dev) != cudaSuccess ||
        cudaDeviceGetAttribute(&nsm, cudaDevAttrMultiProcessorCount, dev) != cudaSuccess ||
        nsm <= 0)
        nsm = 148;

    cudaFuncSetAttribute(k_all, cudaFuncAttributeMaxDynamicSharedMemorySize, SM_TOTAL);
    k_all<<<nsm * 2, 256, SM_TOTAL>>>(f, lab32, out);
}

// round 10
// speedup vs baseline: 1.1818x; 1.1818x over previous
#include <cuda_runtime.h>
#include <cuda_fp16.h>

#define NPTS 8192
#define DIM  128
#define TILE 128
#define NT   (NPTS/TILE)          // 64
#define NTILES (NT*(NT+1)/2)      // 2080
#define MARGIN 1.0f
#define EPSV 1e-16f
#define PAIR_CAP 2500000

// ---------------- device scratch ----------------
__device__ float g_S[NPTS];
__device__ float g_sq[NPTS];
__device__ int   g_lab[NPTS];
__device__ double g_loss;
__device__ unsigned long long g_cnt;
__device__ unsigned g_np;
__device__ unsigned g_done;
__device__ uint4 g_h[NPTS*DIM/8];    // fp16 features, 8 per uint4
__device__ uint2 g_pairs[PAIR_CAP];

// ---------------- smem layout (bytes) ----------------
#define SM_AH   0
#define SM_B(b) (32768 + (b)*32768)
#define SM_MISC 98304
#define SM_SQI  (SM_MISC)                    // 512
#define SM_LI   (SM_MISC + 512)              // 512
#define SM_SQJ(p) (SM_MISC + 1024 + (p)*512) // 2x512
#define SM_LJ(p)  (SM_MISC + 2048 + (p)*512) // 2x512
#define SM_ROWS (SM_MISC + 3072)             // 512
#define SM_CNT  (SM_MISC + 3584)
#define SM_PBUF (SM_MISC + 3616)
#define PBUF_CAP 1024
#define SM_TOTAL (SM_PBUF + PBUF_CAP*8)

__device__ __forceinline__ unsigned smem_u32(const void* p) {
    unsigned a;
    asm("{ .reg .u64 t; cvta.to.shared.u64 t, %1; cvt.u32.u64 %0, t; }" : "=r"(a) : "l"(p));
    return a;
}

#define LDGSTS16(dst, src) asm volatile("cp.async.cg.shared.global [%0], [%1], 16;" :: "r"(dst), "l"(src) : "memory")
#define CP_COMMIT() asm volatile("cp.async.commit_group;" ::: "memory")
#define CP_WAIT1()  asm volatile("cp.async.wait_group 1;" ::: "memory")
#define CP_WAIT0()  asm volatile("cp.async.wait_group 0;" ::: "memory")

#define LDSM4(R, a) asm volatile( \
    "ldmatrix.sync.aligned.m8n8.x4.shared.b16 {%0,%1,%2,%3}, [%4];" \
    : "=r"((R)[0]), "=r"((R)[1]), "=r"((R)[2]), "=r"((R)[3]) : "r"(a))

#define MMA(d, a, b) asm volatile( \
    "mma.sync.aligned.m16n8k16.row.col.f32.f16.f16.f32 " \
    "{%0,%1,%2,%3}, {%4,%5,%6,%7}, {%8,%9}, {%0,%1,%2,%3};" \
    : "+f"((d)[0]), "+f"((d)[1]), "+f"((d)[2]), "+f"((d)[3]) \
    : "r"((a)[0]), "r"((a)[1]), "r"((a)[2]), "r"((a)[3]), "r"((b)[0]), "r"((b)[1]))

// ---------------- fused prep: fp16 convert + sq + labels + init ----------------
// 256 blocks x 256 threads; each thread handles granules g and g+65536 (MLP 4)
__global__ void __launch_bounds__(256) k_prep(const float* __restrict__ f,
                                              const int* __restrict__ lab32) {
    const int b = blockIdx.x, t = threadIdx.x;
    const int g0 = b * 256 + t;                  // first granule
    const float4* f4 = (const float4*)f;
    #pragma unroll
    for (int half = 0; half < 2; half++) {
        const int idx = g0 + half * 65536;
        float4 a = f4[idx * 2], c = f4[idx * 2 + 1];
        __half2 h0 = __floats2half2_rn(a.x, a.y);
        __half2 h1 = __floats2half2_rn(a.z, a.w);
        __half2 h2 = __floats2half2_rn(c.x, c.y);
        __half2 h3 = __floats2half2_rn(c.z, c.w);
        g_h[idx] = make_uint4(*(unsigned*)&h0, *(unsigned*)&h1, *(unsigned*)&h2, *(unsigned*)&h3);
        float s = 0.0f;
        s = fmaf(a.x, a.x, s); s = fmaf(a.y, a.y, s);
        s = fmaf(a.z, a.z, s); s = fmaf(a.w, a.w, s);
        s = fmaf(c.x, c.x, s); s = fmaf(c.y, c.y, s);
        s = fmaf(c.z, c.z, s); s = fmaf(c.w, c.w, s);
        s += __shfl_xor_sync(0xffffffffu, s, 1);
        s += __shfl_xor_sync(0xffffffffu, s, 2);
        s += __shfl_xor_sync(0xffffffffu, s, 4);
        s += __shfl_xor_sync(0xffffffffu, s, 8);
        if ((t & 15) == 0) g_sq[idx >> 4] = s;
    }
    // labels + init (blocks 0..31 cover all 8192 points)
    if (b < 32) {
        const int idx = b * 256 + t;
        int odd = lab32[2 * t + 1];
        int nz = __syncthreads_or(odd != 0);     // nz -> int32 labels
        g_lab[idx] = lab32[idx * (nz ? 1 : 2)];
        g_S[idx] = 0.0f;
        if (idx == 0) { g_loss = 0.0; g_cnt = 0ull; g_np = 0u; g_done = 0u; }
    }
}

// ---------------- stage helpers ----------------
// 256B rows, 16B granules, swizzle: granule q at row r -> q ^ (r&7)
__device__ __forceinline__ void issue_B(unsigned sb, int buf, int jt, int t) {
    const char* sh = (const char*)(g_h + (size_t)jt * 2048);
    const unsigned db = sb + SM_B(buf);
    #pragma unroll
    for (int i = 0; i < 8; i++) {
        int g = i * 256 + t;
        int r = g >> 4, q = g & 15;
        unsigned dsw = (unsigned)(r * 256 + ((q ^ (r & 7)) << 4));
        LDGSTS16(db + dsw, sh + (size_t)g * 16);
    }
}
__device__ __forceinline__ void load_A(char* smem, int it, int t) {
    const uint4* sh = g_h + (size_t)it * 2048;
    #pragma unroll
    for (int i = 0; i < 8; i++) {
        int g = i * 256 + t;
        int r = g >> 4, q = g & 15;
        unsigned dsw = (unsigned)(r * 256 + ((q ^ (r & 7)) << 4));
        *(uint4*)(smem + SM_AH + dsw) = sh[g];
    }
}

// warp-0-only pair flush: pbuf -> g_pairs, no block barrier needed
__device__ __forceinline__ void flush_pairs_w0(unsigned* s_cnt, uint2* pbuf, int lane) {
    unsigned cnt = *s_cnt;
    if (cnt > PBUF_CAP) cnt = PBUF_CAP;
    unsigned gb = 0;
    if (lane == 0 && cnt) gb = atomicAdd(&g_np, cnt);
    gb = __shfl_sync(0xffffffffu, gb, 0);
    for (unsigned i = lane; i < cnt; i += 32) g_pairs[gb + i] = pbuf[i];
    if (lane == 0) *s_cnt = 0u;
}

// ---------------- persistent HMMA Gram + fused epilogue ----------------
__global__ void __launch_bounds__(256, 2) k_S() {
    extern __shared__ char smem[];
    const unsigned sb = smem_u32(smem);
    float* s_sqi  = (float*)(smem + SM_SQI);
    int*   s_li   = (int*)  (smem + SM_LI);
    float* s_rowS = (float*)(smem + SM_ROWS);
    unsigned* s_cnt = (unsigned*)(smem + SM_CNT);
    uint2* pbuf = (uint2*)(smem + SM_PBUF);

    const int t = threadIdx.x, w = t >> 5, lane = t & 31;

    // balanced contiguous split
    const int nb_ = gridDim.x;
    const int basec = NTILES / nb_, rem = NTILES % nb_;
    const int start = blockIdx.x * basec + min(blockIdx.x, rem);
    const int end = start + basec + (blockIdx.x < rem ? 1 : 0);
    if (start >= end) return;

    int cit = 0, base = 0;
    while (start >= base + (NT - cit)) { base += NT - cit; cit++; }
    int cjt = cit + (start - base);

    // prefetch pipeline (depth 2)
    int pit = cit, pjt = cjt;
    issue_B(sb, start & 1, pjt, t); CP_COMMIT();
    { pjt++; if (pjt == NT) { pit++; pjt = pit; } }
    if (start + 1 < end) {
        issue_B(sb, (start + 1) & 1, pjt, t); CP_COMMIT();
        pjt++; if (pjt == NT) { pit++; pjt = pit; }
    }

    if (t == 0) *s_cnt = 0u;

    // warp subtile: 32 rows x 64 cols
    const int mb = (w & 3) * 32;
    const int nb = (w >> 2) * 64;
    const int a_row = mb + (lane & 15);
    const int a_ch  = lane >> 4;
    const int b_row = nb + (lane & 7) + ((lane >> 4) << 3);
    const int b_ch  = (lane >> 3) & 1;

    int curA = -1;
    bool havePrev = false;

    for (int k = start; k < end; k++) {
        const int buf = k & 1;
        const bool offdiag = (cit != cjt);
        if (k + 1 < end) CP_WAIT1(); else CP_WAIT0();

        if (cit != curA) {                        // uniform condition
            __syncthreads();                      // epilogue of prev tile done
            if (curA >= 0 && t < 128) atomicAdd(&g_S[curA * TILE + t], s_rowS[t]);
            load_A(smem, cit, t);
            if (t < 128) {
                s_sqi[t] = g_sq[cit * TILE + t];
                s_li[t]  = g_lab[cit * TILE + t];
                s_rowS[t] = 0.0f;
            }
            curA = cit;
        }
        float* s_sqj = (float*)(smem + SM_SQJ(buf));
        int*   s_lj  = (int*)  (smem + SM_LJ(buf));
        if (t < 128) {
            s_sqj[t] = g_sq[cjt * TILE + t];
            s_lj[t]  = g_lab[cjt * TILE + t];
        }
        __syncthreads();   // SYNC1: B visible block-wide, staging + A visible,
                           //        prev-tile epilogue (pbuf writes) complete

        // warp 0: flush previous tile's pair buffer while others head into MMA
        if (w == 0 && havePrev) flush_pairs_w0(s_cnt, pbuf, lane);
        havePrev = true;

        // ---- MMA: single fp16 product ----
        float acc[2][8][4];
        #pragma unroll
        for (int mt = 0; mt < 2; mt++)
            #pragma unroll
            for (int nt = 0; nt < 8; nt++)
                #pragma unroll
                for (int e = 0; e < 4; e++) acc[mt][nt][e] = 0.0f;

        const unsigned bbase = sb + SM_B(buf);
        #pragma unroll
        for (int ks = 0; ks < 8; ks++) {
            unsigned ah[2][4], bh[8][2];
            #pragma unroll
            for (int mt = 0; mt < 2; mt++) {
                int r = a_row + mt * 16;
                unsigned addr = sb + SM_AH + r * 256 + (((ks * 2 + a_ch) ^ (r & 7)) << 4);
                LDSM4(ah[mt], addr);
            }
            #pragma unroll
            for (int np = 0; np < 4; np++) {
                int r = b_row + np * 16;
                unsigned addr = bbase + r * 256 + (((ks * 2 + b_ch) ^ (r & 7)) << 4);
                unsigned th[4];
                LDSM4(th, addr);
                bh[2*np][0] = th[0]; bh[2*np][1] = th[1];
                bh[2*np+1][0] = th[2]; bh[2*np+1][1] = th[3];
            }
            #pragma unroll
            for (int mt = 0; mt < 2; mt++)
                #pragma unroll
                for (int nt = 0; nt < 8; nt++)
                    MMA(acc[mt][nt], ah[mt], bh[nt]);
        }
        __syncthreads();   // SYNC2: B consumed; warp0's flush + s_cnt reset ordered
                           //        before this tile's epilogue pbuf writes

        // prefetch B(k+2) into this buffer; overlaps epilogue
        if (k + 2 < end) {
            issue_B(sb, buf, pjt, t); CP_COMMIT();
            pjt++; if (pjt == NT) { pit++; pjt = pit; }
        }

        // ---- epilogue ----
        const int r4 = lane >> 2, cb = (lane & 3) * 2;
        float sqi_r[4]; int li_r[4];
        #pragma unroll
        for (int mt = 0; mt < 2; mt++)
            #pragma unroll
            for (int h = 0; h < 2; h++) {
                int iL = mb + mt * 16 + r4 + h * 8;
                sqi_r[mt*2+h] = s_sqi[iL]; li_r[mt*2+h] = s_li[iL];
            }

        float rp[4] = {0.f, 0.f, 0.f, 0.f};
        float cp[16];
        #pragma unroll
        for (int q = 0; q < 16; q++) cp[q] = 0.0f;

        #pragma unroll
        for (int mt = 0; mt < 2; mt++)
            #pragma unroll
            for (int nt = 0; nt < 8; nt++)
                #pragma unroll
                for (int e = 0; e < 4; e++) {
                    const int h = e >> 1, o = e & 1;
                    const int jL = nb + nt * 8 + cb + o;
                    float d2 = fmaxf(sqi_r[mt*2+h] + s_sqj[jL] - 2.0f * acc[mt][nt][e], EPSV);
                    float d;
                    asm("sqrt.approx.f32 %0, %1;" : "=f"(d) : "f"(d2));
                    if (li_r[mt*2+h] != s_lj[jL]) {
                        float ex = __expf(MARGIN - d);
                        rp[mt*2+h] += ex;
                        cp[nt*2+o] += ex;
                    } else {
                        unsigned kk = atomicAdd(s_cnt, 1u);
                        unsigned gi = cit * TILE + mb + mt * 16 + r4 + h * 8;
                        unsigned gj = cjt * TILE + jL;
                        unsigned packed = gi | (gj << 13) | (offdiag ? (1u << 26) : 0u);
                        uint2 rec = make_uint2(packed, __float_as_uint(d));
                        if (kk < PBUF_CAP) pbuf[kk] = rec;
                        else { unsigned gg = atomicAdd(&g_np, 1u); if (gg < PAIR_CAP) g_pairs[gg] = rec; }
                    }
                }

        // row sums -> smem (band-accumulated)
        #pragma unroll
        for (int q = 0; q < 4; q++) {
            float v = rp[q];
            v += __shfl_xor_sync(0xffffffffu, v, 1);
            v += __shfl_xor_sync(0xffffffffu, v, 2);
            if ((lane & 3) == 0)
                atomicAdd(&s_rowS[mb + (q >> 1) * 16 + r4 + (q & 1) * 8], v);
        }
        // col sums -> direct global RED (fire-and-forget)
        if (offdiag) {
            #pragma unroll
            for (int q = 0; q < 16; q++) {
                float v = cp[q];
                v += __shfl_xor_sync(0xffffffffu, v, 4);
                v += __shfl_xor_sync(0xffffffffu, v, 8);
                v += __shfl_xor_sync(0xffffffffu, v, 16);
                if ((lane >> 2) == 0)
                    atomicAdd(&g_S[cjt * TILE + nb + (q >> 1) * 8 + cb + (q & 1)], v);
            }
        }

        cjt++; if (cjt == NT) { cit++; cjt = cit; }
    }

    __syncthreads();       // last tile's epilogue complete
    if (curA >= 0 && t < 128) atomicAdd(&g_S[curA * TILE + t], s_rowS[t]);
    if (w == 0) flush_pairs_w0(s_cnt, pbuf, lane);
}

// ---------------- positive-pair loss + fused finalize ----------------
__global__ void __launch_bounds__(256) k_pairs(float* out) {
    __shared__ float rf[256];
    __shared__ int   ri[256];
    unsigned n = g_np; if (n > PAIR_CAP) n = PAIR_CAP;
    float part = 0.0f; int c = 0;
    for (unsigned idx = blockIdx.x * 256u + threadIdx.x; idx < n; idx += gridDim.x * 256u) {
        uint2 p = g_pairs[idx];
        int i = p.x & 0x1FFF, j = (p.x >> 13) & 0x1FFF;
        int wt = (p.x & (1u << 26)) ? 2 : 1;
        float d = __uint_as_float(p.y);
        float J = __logf(g_S[i] + g_S[j]) + d;
        float h = fmaxf(J, 0.0f);
        part += (float)wt * h * h; c += wt;
    }
    int t = threadIdx.x;
    rf[t] = part; ri[t] = c;
    __syncthreads();
    for (int off = 128; off; off >>= 1) {
        if (t < off) { rf[t] += rf[t + off]; ri[t] += ri[t + off]; }
        __syncthreads();
    }
    if (t == 0) {
        atomicAdd(&g_loss, (double)rf[0]);
        atomicAdd(&g_cnt, (unsigned long long)ri[0]);
        __threadfence();
        unsigned v = atomicAdd(&g_done, 1u);
        if (v == gridDim.x - 1)
            out[0] = (float)(g_loss / (2.0 * (double)g_cnt));
    }
}

// ---------------- launcher ----------------
extern "C" void kernel_launch(void* const* d_in, const int* in_sizes, int n_in,
                              void* d_out, int out_size) {
    const float* f     = (const float*)d_in[0];
    const int*   lab32 = (const int*)d_in[1];
    float*       out   = (float*)d_out;

    int dev = 0, nsm = 0;
    if (cudaGetDevice(&dev) != cudaSuccess ||
        cudaDeviceGetAttribute(&nsm, cudaDevAttrMultiProcessorCount, dev) != cudaSuccess ||
        nsm <= 0)
        nsm = 148;

    cudaFuncSetAttribute(k_S, cudaFuncAttributeMaxDynamicSharedMemorySize, SM_TOTAL);

    k_prep<<<256, 256>>>(f, lab32);
    k_S<<<nsm * 2, 256, SM_TOTAL>>>();
    k_pairs<<<512, 256>>>(out);
}